// round 15
// baseline (speedup 1.0000x reference)
#include <cuda_runtime.h>

// GaussianBlurDM, round 14: 2x data reuse per load (32-row tiles, 16 accs).
//
// out[b] = reflect-conv(reflect-conv(x[b], K_t, axis=H), K_t, axis=W),
// K_t = t-fold self-convolution of the 11-tap Gaussian (exact DCT-I identity),
// truncated at tail mass 2.5e-4.
//
// R13 accounting: FFMAs already issue at ~0.55/cy/SMSP; the issue gap is load
// stalls (L1tex 44%). Fix: each thread owns 16 float2 accumulators fed by a
// 16-slot float2 ring -> one 8B load per 32 lane-FMAs (2x R13), halving both
// V-phase LDG and H-phase LDS counts per output. CTA = 32x256 tile, 3 CTAs/SM.

#define BATCH 64
#define CHAN 3
#define IMG 256
#define NT 19
#define KW 80              // weight array length
#define SVSTRIDE 34        // floats per sv column (32 rows + 2 pad)
#define SV_F2 (SVSTRIDE / 2)   // 17 float2 per column stride

// ---------------------------------------------------------------------------
// Compile-time weight table.
// ---------------------------------------------------------------------------
struct KTab {
    float w[NT][KW];
    int nd[NT];
    int rl[NT];
};

constexpr KTab make_ktab() {
    KTab T{};
    // q = e^{-1/8} by Taylor (full double precision)
    double q = 1.0;
    {
        double term = 1.0;
        for (int i = 1; i < 26; ++i) { term *= (-0.125) / (double)i; q += term; }
    }
    // base pdf[x] = q^(x^2), x = -5..5 ; f32-rounded normalized (matches _k1d)
    double base[11] = {};
    double sum = 0.0;
    for (int x = -5; x <= 5; ++x) {
        double p = 1.0;
        for (int i = 0; i < x * x; ++i) p *= q;
        base[x + 5] = p;
        sum += p;
    }
    for (int i = 0; i < 11; ++i) base[i] = (double)((float)(base[i] / sum));

    double f[220] = {};
    for (int i = 0; i < 11; ++i) f[i] = base[i];
    int hw = 5;
    for (int tt = 1; tt <= NT; ++tt) {
        double acc = 0.0;
        int r = 0;
        for (int a = hw; a >= 1; --a) {
            acc += f[hw + a];
            if (2.0 * acc > 2.5e-4) { r = a; break; }
        }
        T.nd[tt - 1] = 2 * r + 1;
        T.rl[tt - 1] = r;
        for (int j = 0; j <= 2 * r; ++j) T.w[tt - 1][j] = (float)f[hw + j - r];
        if (tt < NT) {                       // f = f (*) base
            double g[220] = {};
            int L = 2 * hw + 1;
            for (int n = 0; n < L; ++n) {
                double fn = f[n];
                for (int k = 0; k < 11; ++k) g[n + k] += fn * base[k];
            }
            for (int i = 0; i < 220; ++i) f[i] = g[i];
            hw += 5;
        }
    }
    return T;
}
constexpr KTab KT = make_ktab();

struct BlurParams { float K[NT][KW]; };   // runtime copy for boundary paths

__device__ __forceinline__ int reflect256(int v) {
    v = abs(v);
    return (v > 255) ? (510 - v) : v;
}

// ---------------------------------------------------------------------------
// Template-recursive unrolled tap loops: 16 f2 accs, 16-slot f2 ring,
// immediate weights, immediate-offset refills.
// ---------------------------------------------------------------------------
template<int TI, int J>
struct VTap {
    static __device__ __forceinline__ void run(
        float2 (&acc)[16], float2 (&ring)[16], const float2* __restrict__ p)
    {
        constexpr float W = KT.w[TI][J];
        #pragma unroll
        for (int k = 0; k < 16; ++k) {
            float2 r = ring[(J + k) & 15];
            acc[k].x = fmaf(r.x, W, acc[k].x);
            acc[k].y = fmaf(r.y, W, acc[k].y);
        }
        if constexpr (J + 1 < KT.nd[TI]) {
            ring[J & 15] = __ldg(p + ((J + 16) << 7));   // row stride 128 f2
            VTap<TI, J + 1>::run(acc, ring, p);
        }
    }
};

template<int TI, int J>
struct HTap {
    static __device__ __forceinline__ void run(
        float2 (&acc)[16], float2 (&ring)[16], const float2* __restrict__ p)
    {
        constexpr float W = KT.w[TI][J];
        #pragma unroll
        for (int k = 0; k < 16; ++k) {
            float2 r = ring[(J + k) & 15];
            acc[k].x = fmaf(r.x, W, acc[k].x);
            acc[k].y = fmaf(r.y, W, acc[k].y);
        }
        if constexpr (J + 1 < KT.nd[TI]) {
            ring[J & 15] = p[(J + 16) * SV_F2];          // smem col stride
            HTap<TI, J + 1>::run(acc, ring, p);
        }
    }
};

// ---------------------------------------------------------------------------
// Epilogues.
// ---------------------------------------------------------------------------
// V: thread owns cols (c0,c0+1), rows mr..mr+15 -> sv[col][row] transposed.
__device__ __forceinline__ void store_sv(float* sv, int cp_, int half,
                                         const float2 (&acc)[16])
{
    const int c0 = cp_ << 1;
    float* q0 = sv + c0 * SVSTRIDE + (half << 4);
    float* q1 = sv + (c0 + 1) * SVSTRIDE + (half << 4);
    #pragma unroll
    for (int q = 0; q < 8; ++q) {
        *(float2*)(q0 + 2 * q) = make_float2(acc[2 * q].x, acc[2 * q + 1].x);
        *(float2*)(q1 + 2 * q) = make_float2(acc[2 * q].y, acc[2 * q + 1].y);
    }
}

// H: thread owns rows (m0+2rp, m0+2rp+1), cols cg*16..+15.
__device__ __forceinline__ void store_out(float* gout, int m0, int rp, int cg,
                                          const float2 (&acc)[16])
{
    float4* d0 = (float4*)(gout + (m0 + 2 * rp) * IMG + (cg << 4));
    float4* d1 = (float4*)(gout + (m0 + 2 * rp + 1) * IMG + (cg << 4));
    #pragma unroll
    for (int q = 0; q < 4; ++q) {
        d0[q] = make_float4(acc[4 * q].x, acc[4 * q + 1].x,
                            acc[4 * q + 2].x, acc[4 * q + 3].x);
        d1[q] = make_float4(acc[4 * q].y, acc[4 * q + 1].y,
                            acc[4 * q + 2].y, acc[4 * q + 3].y);
    }
}

// ---------------------------------------------------------------------------
// Boundary paths (runtime weights; one copy each).
// ---------------------------------------------------------------------------
__device__ __noinline__ void v_boundary(
    const float2* __restrict__ scol, float* __restrict__ sv,
    int cp_, int half, int vb, const float* __restrict__ Kf, int ndp)
{
    float2 acc[16] = {};
    float2 ring[16];
    #pragma unroll
    for (int m = 0; m < 16; ++m)
        ring[m] = __ldg(scol + (reflect256(vb + m) << 7));
    #pragma unroll 1
    for (int jj = 0; jj < ndp; jj += 8) {
        #pragma unroll
        for (int u = 0; u < 8; ++u) {
            float W = Kf[jj + u];
            #pragma unroll
            for (int k = 0; k < 16; ++k) {
                float2 r = ring[(jj + u + k) & 15];
                acc[k].x = fmaf(r.x, W, acc[k].x);
                acc[k].y = fmaf(r.y, W, acc[k].y);
            }
            ring[(jj + u) & 15] =
                __ldg(scol + (reflect256(vb + jj + u + 16) << 7));
        }
    }
    store_sv(sv, cp_, half, acc);
}

__device__ __noinline__ void h_boundary(
    const float2* __restrict__ sb, float* __restrict__ gout,
    int rp, int cg, int qb, const float* __restrict__ Kf, int ndp, int m0)
{
    float2 acc[16] = {};
    float2 ring[16];
    #pragma unroll
    for (int m = 0; m < 16; ++m)
        ring[m] = sb[reflect256(qb + m) * SV_F2];
    #pragma unroll 1
    for (int jj = 0; jj < ndp; jj += 8) {
        #pragma unroll
        for (int u = 0; u < 8; ++u) {
            float W = Kf[jj + u];
            #pragma unroll
            for (int k = 0; k < 16; ++k) {
                float2 r = ring[(jj + u + k) & 15];
                acc[k].x = fmaf(r.x, W, acc[k].x);
                acc[k].y = fmaf(r.y, W, acc[k].y);
            }
            ring[(jj + u) & 15] = sb[reflect256(qb + jj + u + 16) * SV_F2];
        }
    }
    store_out(gout, m0, rp, cg, acc);
}

// ---------------------------------------------------------------------------
// Per-t tile body.
// ---------------------------------------------------------------------------
template<int TI>
__device__ __forceinline__ void tile_body(
    const float* __restrict__ img, float* __restrict__ gout, float* sv,
    int tid, int m0, const float* __restrict__ KfT)
{
    constexpr int ND = KT.nd[TI];
    constexpr int RL = KT.rl[TI];
    constexpr int NDP = (ND + 7) & ~7;

    // ---- V phase: thread = column pair x 16-row half of the 32-row tile ----
    {
        const int cp_ = tid & 127;
        const int half = tid >> 7;
        const float2* scol = (const float2*)img + cp_;
        const int vb = m0 + (half << 4) - RL;
        if (vb >= 0 && vb + ND + 15 <= 255) {
            float2 acc[16] = {};
            float2 ring[16];
            const float2* p = scol + (vb << 7);
            #pragma unroll
            for (int m = 0; m < 16; ++m) ring[m] = __ldg(p + (m << 7));
            VTap<TI, 0>::run(acc, ring, p);
            store_sv(sv, cp_, half, acc);
        } else {
            v_boundary(scol, sv, cp_, half, vb, KfT, NDP);
        }
    }

    __syncthreads();

    // ---- H phase: thread = row pair (16) x 16-col group (16) ----
    {
        const int rp = tid & 15;
        const int cg = tid >> 4;
        const float2* sb = (const float2*)sv + rp;
        const int qb = (cg << 4) - RL;
        if (qb >= 0 && qb + ND + 15 <= 255) {
            float2 acc[16] = {};
            float2 ring[16];
            const float2* p = sb + qb * SV_F2;
            #pragma unroll
            for (int m = 0; m < 16; ++m) ring[m] = p[m * SV_F2];
            HTap<TI, 0>::run(acc, ring, p);
            store_out(gout, m0, rp, cg, acc);
        } else {
            h_boundary(sb, gout, rp, cg, qb, KfT, NDP, m0);
        }
    }
}

// ---------------------------------------------------------------------------
__global__ void __launch_bounds__(256, 3) blur_fused(
    const float* __restrict__ src, float* __restrict__ dst,
    const int* __restrict__ t, const __grid_constant__ BlurParams P)
{
    __shared__ float sv[IMG * SVSTRIDE];            // 34816 B

    const int tid = threadIdx.x;
    const int m0 = blockIdx.x << 5;                 // tile's first output row
    const int bc = blockIdx.z * CHAN + blockIdx.y;
    const float* img = src + ((long)bc << 16);
    float* gout = dst + ((long)bc << 16);

    const int tb = t[blockIdx.z];
    if (tb <= 0) {                                  // identity (safety)
        const float4* s4 = (const float4*)(img + (m0 << 8));
        float4* d4 = (float4*)(gout + (m0 << 8));
        #pragma unroll
        for (int i = 0; i < 8; ++i) d4[tid + 256 * i] = s4[tid + 256 * i];
        return;
    }
    const int ti = (tb > NT) ? (NT - 1) : (tb - 1);

    switch (ti) {
#define CASE_TI(TI) case TI: tile_body<TI>(img, gout, sv, tid, m0, P.K[TI]); break;
        CASE_TI(0)  CASE_TI(1)  CASE_TI(2)  CASE_TI(3)  CASE_TI(4)
        CASE_TI(5)  CASE_TI(6)  CASE_TI(7)  CASE_TI(8)  CASE_TI(9)
        CASE_TI(10) CASE_TI(11) CASE_TI(12) CASE_TI(13) CASE_TI(14)
        CASE_TI(15) CASE_TI(16) CASE_TI(17) CASE_TI(18)
#undef CASE_TI
        default: break;
    }
}

// ---------------------------------------------------------------------------
extern "C" void kernel_launch(void* const* d_in, const int* in_sizes, int n_in,
                              void* d_out, int out_size) {
    const float* x = (const float*)d_in[0];
    const int* t = (const int*)d_in[1];
    float* out = (float*)d_out;

    // Runtime weight copy for boundary paths (zero-padded to 8-multiples).
    static BlurParams P = {};
    for (int ti = 0; ti < NT; ++ti) {
        for (int j = 0; j < KW; ++j)
            P.K[ti][j] = (j < KT.nd[ti]) ? KT.w[ti][j] : 0.0f;
    }

    dim3 block(256);
    dim3 grid(IMG / 32, CHAN, BATCH);   // 8 x 3 x 64 = 1536 CTAs
    blur_fused<<<grid, block>>>(x, out, t, P);
}

// round 16
// speedup vs baseline: 1.6899x; 1.6899x over previous
#include <cuda_runtime.h>

// GaussianBlurDM, round 15: R13 structure + 16-slot ring (long refill distance).
//
// out[b] = reflect-conv(reflect-conv(x[b], K_t, axis=H), K_t, axis=W),
// K_t = t-fold self-convolution of the 11-tap Gaussian (exact DCT-I identity),
// truncated at tail mass 2.5e-4.
//
// R12/R13 plateau diagnosis: FFMAs retire at ~0.55/cy/SMSP; the gap to full
// issue is refill stalls -- the 8-slot ring reloads row J+8 at tap J and reads
// it at tap J+1 (~16 issue slots < 29cy LDS / ~260cy L2). Fix: 16-slot ring,
// refill row J+16 at tap J, first read at tap J+9 (~144 slots/warp, x4 warps
// per SMSP). Tile stays 16x256 (R14's 32-row tiles blew up code size/regs).

#define BATCH 64
#define CHAN 3
#define IMG 256
#define NT 19
#define KW 80              // weight array length
#define SVSTRIDE 18        // floats per sv column (16 rows + 2 pad)
#define SV_F2 (SVSTRIDE / 2)

// ---------------------------------------------------------------------------
// Compile-time weight table.
// ---------------------------------------------------------------------------
struct KTab {
    float w[NT][KW];
    int nd[NT];
    int rl[NT];
};

constexpr KTab make_ktab() {
    KTab T{};
    // q = e^{-1/8} by Taylor (full double precision)
    double q = 1.0;
    {
        double term = 1.0;
        for (int i = 1; i < 26; ++i) { term *= (-0.125) / (double)i; q += term; }
    }
    // base pdf[x] = q^(x^2), x = -5..5 ; f32-rounded normalized (matches _k1d)
    double base[11] = {};
    double sum = 0.0;
    for (int x = -5; x <= 5; ++x) {
        double p = 1.0;
        for (int i = 0; i < x * x; ++i) p *= q;
        base[x + 5] = p;
        sum += p;
    }
    for (int i = 0; i < 11; ++i) base[i] = (double)((float)(base[i] / sum));

    double f[220] = {};
    for (int i = 0; i < 11; ++i) f[i] = base[i];
    int hw = 5;
    for (int tt = 1; tt <= NT; ++tt) {
        double acc = 0.0;
        int r = 0;
        for (int a = hw; a >= 1; --a) {
            acc += f[hw + a];
            if (2.0 * acc > 2.5e-4) { r = a; break; }
        }
        T.nd[tt - 1] = 2 * r + 1;
        T.rl[tt - 1] = r;
        for (int j = 0; j <= 2 * r; ++j) T.w[tt - 1][j] = (float)f[hw + j - r];
        if (tt < NT) {                       // f = f (*) base
            double g[220] = {};
            int L = 2 * hw + 1;
            for (int n = 0; n < L; ++n) {
                double fn = f[n];
                for (int k = 0; k < 11; ++k) g[n + k] += fn * base[k];
            }
            for (int i = 0; i < 220; ++i) f[i] = g[i];
            hw += 5;
        }
    }
    return T;
}
constexpr KTab KT = make_ktab();

struct BlurParams { float K[NT][KW]; };   // runtime copy for boundary paths

__device__ __forceinline__ int reflect256(int v) {
    v = abs(v);
    return (v > 255) ? (510 - v) : v;
}

// ---------------------------------------------------------------------------
// Template-recursive unrolled tap loops: 8 scalar acc pairs, 16-slot f2 ring.
// Tap J reads rows J..J+7 (slots (J+k)&15); refills slot J&15 with row J+16,
// first consumed at tap J+9.
// ---------------------------------------------------------------------------
template<int TI, int J>
struct VTap {
    static __device__ __forceinline__ void run(
        float (&ax)[8], float (&ay)[8], float2 (&ring)[16],
        const float2* __restrict__ p)
    {
        constexpr float W = KT.w[TI][J];
        #pragma unroll
        for (int k = 0; k < 8; ++k) {
            float2 r = ring[(J + k) & 15];
            ax[k] = fmaf(r.x, W, ax[k]);
            ay[k] = fmaf(r.y, W, ay[k]);
        }
        if constexpr (J + 16 < KT.nd[TI] + 7)
            ring[J & 15] = __ldg(p + ((J + 16) << 7));   // row stride 128 f2
        if constexpr (J + 1 < KT.nd[TI])
            VTap<TI, J + 1>::run(ax, ay, ring, p);
    }
};

template<int TI, int J>
struct HTap {
    static __device__ __forceinline__ void run(
        float (&ax)[8], float (&ay)[8], float2 (&ring)[16],
        const float2* __restrict__ p)
    {
        constexpr float W = KT.w[TI][J];
        #pragma unroll
        for (int k = 0; k < 8; ++k) {
            float2 r = ring[(J + k) & 15];
            ax[k] = fmaf(r.x, W, ax[k]);
            ay[k] = fmaf(r.y, W, ay[k]);
        }
        if constexpr (J + 16 < KT.nd[TI] + 7)
            ring[J & 15] = p[(J + 16) * SV_F2];          // smem col stride
        if constexpr (J + 1 < KT.nd[TI])
            HTap<TI, J + 1>::run(ax, ay, ring, p);
    }
};

// ---------------------------------------------------------------------------
// Shared epilogues (identical to R13).
// ---------------------------------------------------------------------------
__device__ __forceinline__ void store_sv(float* sv, int cp_, int half,
                                         const float (&ax)[8],
                                         const float (&ay)[8])
{
    const int c0 = cp_ << 1;
    float* q0 = sv + c0 * SVSTRIDE + (half << 3);
    float* q1 = sv + (c0 + 1) * SVSTRIDE + (half << 3);
    #pragma unroll
    for (int q = 0; q < 4; ++q) {
        *(float2*)(q0 + 2 * q) = make_float2(ax[2 * q], ax[2 * q + 1]);
        *(float2*)(q1 + 2 * q) = make_float2(ay[2 * q], ay[2 * q + 1]);
    }
}

__device__ __forceinline__ void store_out(float* gout, int m0, int rp, int cg,
                                          const float (&ax)[8],
                                          const float (&ay)[8])
{
    float4* d0 = (float4*)(gout + (m0 + 2 * rp) * IMG + (cg << 3));
    float4* d1 = (float4*)(gout + (m0 + 2 * rp + 1) * IMG + (cg << 3));
    d0[0] = make_float4(ax[0], ax[1], ax[2], ax[3]);
    d0[1] = make_float4(ax[4], ax[5], ax[6], ax[7]);
    d1[0] = make_float4(ay[0], ay[1], ay[2], ay[3]);
    d1[1] = make_float4(ay[4], ay[5], ay[6], ay[7]);
}

// ---------------------------------------------------------------------------
// Boundary paths (runtime weights; one copy each; 8-slot ring, proven in R13).
// ---------------------------------------------------------------------------
__device__ __noinline__ void v_boundary(
    const float2* __restrict__ scol, float* __restrict__ sv,
    int cp_, int half, int vb, const float* __restrict__ Kf, int ndp)
{
    float ax[8] = {}, ay[8] = {};
    float2 ring[8];
    #pragma unroll
    for (int m = 0; m < 8; ++m)
        ring[m] = __ldg(scol + (reflect256(vb + m) << 7));
    #pragma unroll 1
    for (int jj = 0; jj < ndp; jj += 8) {
        #pragma unroll
        for (int u = 0; u < 8; ++u) {
            float W = Kf[jj + u];
            #pragma unroll
            for (int k = 0; k < 8; ++k) {
                float2 r = ring[(u + k) & 7];
                ax[k] = fmaf(r.x, W, ax[k]);
                ay[k] = fmaf(r.y, W, ay[k]);
            }
            ring[u] = __ldg(scol + (reflect256(vb + jj + u + 8) << 7));
        }
    }
    store_sv(sv, cp_, half, ax, ay);
}

__device__ __noinline__ void h_boundary(
    const float2* __restrict__ sb, float* __restrict__ gout,
    int rp, int cg, int qb, const float* __restrict__ Kf, int ndp, int m0)
{
    float ax[8] = {}, ay[8] = {};
    float2 ring[8];
    #pragma unroll
    for (int m = 0; m < 8; ++m)
        ring[m] = sb[reflect256(qb + m) * SV_F2];
    #pragma unroll 1
    for (int jj = 0; jj < ndp; jj += 8) {
        #pragma unroll
        for (int u = 0; u < 8; ++u) {
            float W = Kf[jj + u];
            #pragma unroll
            for (int k = 0; k < 8; ++k) {
                float2 r = ring[(u + k) & 7];
                ax[k] = fmaf(r.x, W, ax[k]);
                ay[k] = fmaf(r.y, W, ay[k]);
            }
            ring[u] = sb[reflect256(qb + jj + u + 8) * SV_F2];
        }
    }
    store_out(gout, m0, rp, cg, ax, ay);
}

// ---------------------------------------------------------------------------
// Per-t tile body: V pass (global -> sv transposed), H pass (sv -> out).
// ---------------------------------------------------------------------------
template<int TI>
__device__ __forceinline__ void tile_body(
    const float* __restrict__ img, float* __restrict__ gout, float* sv,
    int tid, int m0, const float* __restrict__ KfT)
{
    constexpr int ND = KT.nd[TI];
    constexpr int RL = KT.rl[TI];
    constexpr int NDP = (ND + 7) & ~7;

    // ---- V phase: thread = column pair x 8 rows ----
    {
        const int cp_ = tid & 127;
        const int half = tid >> 7;
        const float2* scol = (const float2*)img + cp_;
        const int vb = m0 + (half << 3) - RL;
        if (vb >= 0 && vb + ND + 6 <= 255) {
            float ax[8] = {}, ay[8] = {};
            float2 ring[16];
            const float2* p = scol + (vb << 7);
            #pragma unroll
            for (int m = 0; m < 16; ++m) ring[m] = __ldg(p + (m << 7));
            VTap<TI, 0>::run(ax, ay, ring, p);
            store_sv(sv, cp_, half, ax, ay);
        } else {
            v_boundary(scol, sv, cp_, half, vb, KfT, NDP);
        }
    }

    __syncthreads();

    // ---- H phase: thread = row pair x 8 columns ----
    {
        const int rp = tid & 7;
        const int cg = tid >> 3;
        const float2* sb = (const float2*)sv + rp;
        const int qb = (cg << 3) - RL;
        if (qb >= 0 && qb + ND + 6 <= 255) {
            float ax[8] = {}, ay[8] = {};
            float2 ring[16];
            const float2* p = sb + qb * SV_F2;
            #pragma unroll
            for (int m = 0; m < 16; ++m) ring[m] = p[m * SV_F2];
            HTap<TI, 0>::run(ax, ay, ring, p);
            store_out(gout, m0, rp, cg, ax, ay);
        } else {
            h_boundary(sb, gout, rp, cg, qb, KfT, NDP, m0);
        }
    }
}

// ---------------------------------------------------------------------------
__global__ void __launch_bounds__(256, 4) blur_fused(
    const float* __restrict__ src, float* __restrict__ dst,
    const int* __restrict__ t, const __grid_constant__ BlurParams P)
{
    __shared__ float sv[IMG * SVSTRIDE];

    const int tid = threadIdx.x;
    const int m0 = blockIdx.x << 4;                 // tile's first output row
    const int bc = blockIdx.z * CHAN + blockIdx.y;
    const float* img = src + ((long)bc << 16);
    float* gout = dst + ((long)bc << 16);

    const int tb = t[blockIdx.z];
    if (tb <= 0) {                                  // identity (safety)
        const float4* s4 = (const float4*)(img + (m0 << 8));
        float4* d4 = (float4*)(gout + (m0 << 8));
        #pragma unroll
        for (int i = 0; i < 4; ++i) d4[tid + 256 * i] = s4[tid + 256 * i];
        return;
    }
    const int ti = (tb > NT) ? (NT - 1) : (tb - 1);

    switch (ti) {
#define CASE_TI(TI) case TI: tile_body<TI>(img, gout, sv, tid, m0, P.K[TI]); break;
        CASE_TI(0)  CASE_TI(1)  CASE_TI(2)  CASE_TI(3)  CASE_TI(4)
        CASE_TI(5)  CASE_TI(6)  CASE_TI(7)  CASE_TI(8)  CASE_TI(9)
        CASE_TI(10) CASE_TI(11) CASE_TI(12) CASE_TI(13) CASE_TI(14)
        CASE_TI(15) CASE_TI(16) CASE_TI(17) CASE_TI(18)
#undef CASE_TI
        default: break;
    }
}

// ---------------------------------------------------------------------------
extern "C" void kernel_launch(void* const* d_in, const int* in_sizes, int n_in,
                              void* d_out, int out_size) {
    const float* x = (const float*)d_in[0];
    const int* t = (const int*)d_in[1];
    float* out = (float*)d_out;

    // Runtime weight copy for boundary paths (zero-padded to 8-multiples).
    static BlurParams P = {};
    for (int ti = 0; ti < NT; ++ti) {
        for (int j = 0; j < KW; ++j)
            P.K[ti][j] = (j < KT.nd[ti]) ? KT.w[ti][j] : 0.0f;
    }

    dim3 block(256);
    dim3 grid(IMG / 16, CHAN, BATCH);   // 16 x 3 x 64 = 3072 CTAs
    blur_fused<<<grid, block>>>(x, out, t, P);
}

// round 17
// speedup vs baseline: 1.9266x; 1.1401x over previous
#include <cuda_runtime.h>

// GaussianBlurDM, round 16: f32x2 FFMA (2 lanes/instr) + template unroll +
// longest-first CTA scheduling.
//
// Ledger from R12-R15: scalar FFMA issues at ~0.45/cy/SMSP = the rt=2 pipe
// ceiling (imm-form rt=1 not materializing). FFMA2 is rt=3 but gives 0.67
// lane-FMA/cy -- 1.4x. R11's FFMA2 attempt was stall-bound, not pipe-bound;
// this round pairs FFMA2 with the proven stall-free machinery (full template
// unroll, immediate-offset refills, constant-bank weights, 16-slot ring,
// 4 CTAs/SM). Images are processed longest-kernel-first via a tiny pre-kernel.

#define BATCH 64
#define CHAN 3
#define IMG 256
#define NT 19
#define KW 80              // weight array length
#define SVSTRIDE 18        // floats per sv column (16 rows + 2 pad)
#define SV_F2 (SVSTRIDE / 2)   // 9 u64 per column stride

typedef unsigned long long u64;

// ---------------------------------------------------------------------------
// Compile-time weight table.
// ---------------------------------------------------------------------------
struct KTab {
    float w[NT][KW];
    int nd[NT];
    int rl[NT];
};

constexpr KTab make_ktab() {
    KTab T{};
    double q = 1.0;                      // e^{-1/8} by Taylor
    {
        double term = 1.0;
        for (int i = 1; i < 26; ++i) { term *= (-0.125) / (double)i; q += term; }
    }
    double base[11] = {};
    double sum = 0.0;
    for (int x = -5; x <= 5; ++x) {
        double p = 1.0;
        for (int i = 0; i < x * x; ++i) p *= q;
        base[x + 5] = p;
        sum += p;
    }
    for (int i = 0; i < 11; ++i) base[i] = (double)((float)(base[i] / sum));

    double f[220] = {};
    for (int i = 0; i < 11; ++i) f[i] = base[i];
    int hw = 5;
    for (int tt = 1; tt <= NT; ++tt) {
        double acc = 0.0;
        int r = 0;
        for (int a = hw; a >= 1; --a) {
            acc += f[hw + a];
            if (2.0 * acc > 2.5e-4) { r = a; break; }
        }
        T.nd[tt - 1] = 2 * r + 1;
        T.rl[tt - 1] = r;
        for (int j = 0; j <= 2 * r; ++j) T.w[tt - 1][j] = (float)f[hw + j - r];
        if (tt < NT) {
            double g[220] = {};
            int L = 2 * hw + 1;
            for (int n = 0; n < L; ++n) {
                double fn = f[n];
                for (int k = 0; k < 11; ++k) g[n + k] += fn * base[k];
            }
            for (int i = 0; i < 220; ++i) f[i] = g[i];
            hw += 5;
        }
    }
    return T;
}
constexpr KTab KT = make_ktab();

// Weights duplicated into both f32 lanes, in kernel param space (c-bank).
struct BlurParams { float2 K2[NT][KW]; };   // 12160 B

__device__ int g_perm[BATCH];               // longest-first image order

__device__ __forceinline__ int reflect256(int v) {
    v = abs(v);
    return (v > 255) ? (510 - v) : v;
}

__device__ __forceinline__ u64 ffma2(u64 a, u64 b, u64 c) {
    u64 d;
    asm("fma.rn.f32x2 %0, %1, %2, %3;" : "=l"(d) : "l"(a), "l"(b), "l"(c));
    return d;
}

__device__ __forceinline__ void unpack2(u64 v, float& x, float& y) {
    asm("mov.b64 {%0, %1}, %2;" : "=f"(x), "=f"(y) : "l"(v));
}

// ---------------------------------------------------------------------------
// Template-unrolled tap loops: 8 u64 accs, 16-slot u64 ring, weight via
// LDC.64 (compile-time offset), refill with immediate-offset load.
// Tap J reads rows J..J+7; refills slot J&15 with row J+16 (used at J+9).
// ---------------------------------------------------------------------------
template<int TI, int J>
struct VTap {
    static __device__ __forceinline__ void run(
        u64 (&acc)[8], u64 (&ring)[16],
        const u64* __restrict__ p, const u64* __restrict__ Kw)
    {
        u64 w = Kw[J];                               // LDC.64, imm offset
        #pragma unroll
        for (int k = 0; k < 8; ++k)
            acc[k] = ffma2(ring[(J + k) & 15], w, acc[k]);
        if constexpr (J + 16 < KT.nd[TI] + 7)
            ring[J & 15] = __ldg(p + ((J + 16) << 7));   // row stride 128 u64
        if constexpr (J + 1 < KT.nd[TI])
            VTap<TI, J + 1>::run(acc, ring, p, Kw);
    }
};

template<int TI, int J>
struct HTap {
    static __device__ __forceinline__ void run(
        u64 (&acc)[8], u64 (&ring)[16],
        const u64* __restrict__ p, const u64* __restrict__ Kw)
    {
        u64 w = Kw[J];
        #pragma unroll
        for (int k = 0; k < 8; ++k)
            acc[k] = ffma2(ring[(J + k) & 15], w, acc[k]);
        if constexpr (J + 16 < KT.nd[TI] + 7)
            ring[J & 15] = p[(J + 16) * SV_F2];          // smem col stride
        if constexpr (J + 1 < KT.nd[TI])
            HTap<TI, J + 1>::run(acc, ring, p, Kw);
    }
};

// ---------------------------------------------------------------------------
// Epilogues.
// ---------------------------------------------------------------------------
__device__ __forceinline__ void store_sv(float* sv, int cp_, int half,
                                         const u64 (&acc)[8])
{
    float lo[8], hi[8];
    #pragma unroll
    for (int k = 0; k < 8; ++k) unpack2(acc[k], lo[k], hi[k]);
    const int c0 = cp_ << 1;
    float* q0 = sv + c0 * SVSTRIDE + (half << 3);
    float* q1 = sv + (c0 + 1) * SVSTRIDE + (half << 3);
    #pragma unroll
    for (int q = 0; q < 4; ++q) {
        *(float2*)(q0 + 2 * q) = make_float2(lo[2 * q], lo[2 * q + 1]);
        *(float2*)(q1 + 2 * q) = make_float2(hi[2 * q], hi[2 * q + 1]);
    }
}

__device__ __forceinline__ void store_out(float* gout, int m0, int rp, int cg,
                                          const u64 (&acc)[8])
{
    float lo[8], hi[8];
    #pragma unroll
    for (int k = 0; k < 8; ++k) unpack2(acc[k], lo[k], hi[k]);
    float4* d0 = (float4*)(gout + (m0 + 2 * rp) * IMG + (cg << 3));
    float4* d1 = (float4*)(gout + (m0 + 2 * rp + 1) * IMG + (cg << 3));
    d0[0] = make_float4(lo[0], lo[1], lo[2], lo[3]);
    d0[1] = make_float4(lo[4], lo[5], lo[6], lo[7]);
    d1[0] = make_float4(hi[0], hi[1], hi[2], hi[3]);
    d1[1] = make_float4(hi[4], hi[5], hi[6], hi[7]);
}

// ---------------------------------------------------------------------------
// Boundary paths (runtime weights; reflect indexing; one copy each).
// ---------------------------------------------------------------------------
__device__ __noinline__ void v_boundary(
    const u64* __restrict__ scol, float* __restrict__ sv,
    int cp_, int half, int vb, const u64* __restrict__ Kw, int ndp)
{
    u64 acc[8] = {};
    u64 ring[8];
    #pragma unroll
    for (int m = 0; m < 8; ++m)
        ring[m] = __ldg(scol + (reflect256(vb + m) << 7));
    #pragma unroll 1
    for (int jj = 0; jj < ndp; jj += 8) {
        #pragma unroll
        for (int u = 0; u < 8; ++u) {
            u64 w = Kw[jj + u];
            #pragma unroll
            for (int k = 0; k < 8; ++k)
                acc[k] = ffma2(ring[(u + k) & 7], w, acc[k]);
            ring[u] = __ldg(scol + (reflect256(vb + jj + u + 8) << 7));
        }
    }
    store_sv(sv, cp_, half, acc);
}

__device__ __noinline__ void h_boundary(
    const u64* __restrict__ sb, float* __restrict__ gout,
    int rp, int cg, int qb, const u64* __restrict__ Kw, int ndp, int m0)
{
    u64 acc[8] = {};
    u64 ring[8];
    #pragma unroll
    for (int m = 0; m < 8; ++m)
        ring[m] = sb[reflect256(qb + m) * SV_F2];
    #pragma unroll 1
    for (int jj = 0; jj < ndp; jj += 8) {
        #pragma unroll
        for (int u = 0; u < 8; ++u) {
            u64 w = Kw[jj + u];
            #pragma unroll
            for (int k = 0; k < 8; ++k)
                acc[k] = ffma2(ring[(u + k) & 7], w, acc[k]);
            ring[u] = sb[reflect256(qb + jj + u + 8) * SV_F2];
        }
    }
    store_out(gout, m0, rp, cg, acc);
}

// ---------------------------------------------------------------------------
// Per-t tile body.
// ---------------------------------------------------------------------------
template<int TI>
__device__ __forceinline__ void tile_body(
    const float* __restrict__ img, float* __restrict__ gout, float* sv,
    int tid, int m0, const u64* __restrict__ Kw)
{
    constexpr int ND = KT.nd[TI];
    constexpr int RL = KT.rl[TI];
    constexpr int NDP = (ND + 7) & ~7;

    // ---- V phase: thread = column pair x 8 rows ----
    {
        const int cp_ = tid & 127;
        const int half = tid >> 7;
        const u64* scol = (const u64*)img + cp_;
        const int vb = m0 + (half << 3) - RL;
        if (vb >= 0 && vb + ND + 6 <= 255) {
            u64 acc[8] = {};
            u64 ring[16];
            const u64* p = scol + (vb << 7);
            #pragma unroll
            for (int m = 0; m < 16; ++m) ring[m] = __ldg(p + (m << 7));
            VTap<TI, 0>::run(acc, ring, p, Kw);
            store_sv(sv, cp_, half, acc);
        } else {
            v_boundary(scol, sv, cp_, half, vb, Kw, NDP);
        }
    }

    __syncthreads();

    // ---- H phase: thread = row pair x 8 columns ----
    {
        const int rp = tid & 7;
        const int cg = tid >> 3;
        const u64* sb = (const u64*)sv + rp;
        const int qb = (cg << 3) - RL;
        if (qb >= 0 && qb + ND + 6 <= 255) {
            u64 acc[8] = {};
            u64 ring[16];
            const u64* p = sb + qb * SV_F2;
            #pragma unroll
            for (int m = 0; m < 16; ++m) ring[m] = p[m * SV_F2];
            HTap<TI, 0>::run(acc, ring, p, Kw);
            store_out(gout, m0, rp, cg, acc);
        } else {
            h_boundary(sb, gout, rp, cg, qb, Kw, NDP, m0);
        }
    }
}

// ---------------------------------------------------------------------------
// Pre-kernel: longest-kernel-first image order (t descending, stable).
// ---------------------------------------------------------------------------
__global__ void compute_perm(const int* __restrict__ t) {
    const int i = threadIdx.x;                  // 64 threads
    const int ti = t[i];
    int rank = 0;
    for (int j = 0; j < BATCH; ++j) {
        int tj = t[j];
        rank += (tj > ti) || (tj == ti && j < i);
    }
    g_perm[rank] = i;
}

// ---------------------------------------------------------------------------
__global__ void __launch_bounds__(256, 4) blur_fused(
    const float* __restrict__ src, float* __restrict__ dst,
    const int* __restrict__ t, const __grid_constant__ BlurParams P)
{
    __shared__ float sv[IMG * SVSTRIDE];

    const int tid = threadIdx.x;
    const int m0 = blockIdx.x << 4;             // tile's first output row
    const int b = g_perm[blockIdx.z];           // longest-first order
    const int bc = b * CHAN + blockIdx.y;
    const float* img = src + ((long)bc << 16);
    float* gout = dst + ((long)bc << 16);

    const int tb = t[b];
    if (tb <= 0) {                              // identity (safety)
        const float4* s4 = (const float4*)(img + (m0 << 8));
        float4* d4 = (float4*)(gout + (m0 << 8));
        #pragma unroll
        for (int i = 0; i < 4; ++i) d4[tid + 256 * i] = s4[tid + 256 * i];
        return;
    }
    const int ti = (tb > NT) ? (NT - 1) : (tb - 1);
    const u64* Kw = (const u64*)P.K2[ti];

    switch (ti) {
#define CASE_TI(TI) case TI: tile_body<TI>(img, gout, sv, tid, m0, Kw); break;
        CASE_TI(0)  CASE_TI(1)  CASE_TI(2)  CASE_TI(3)  CASE_TI(4)
        CASE_TI(5)  CASE_TI(6)  CASE_TI(7)  CASE_TI(8)  CASE_TI(9)
        CASE_TI(10) CASE_TI(11) CASE_TI(12) CASE_TI(13) CASE_TI(14)
        CASE_TI(15) CASE_TI(16) CASE_TI(17) CASE_TI(18)
#undef CASE_TI
        default: break;
    }
}

// ---------------------------------------------------------------------------
extern "C" void kernel_launch(void* const* d_in, const int* in_sizes, int n_in,
                              void* d_out, int out_size) {
    const float* x = (const float*)d_in[0];
    const int* t = (const int*)d_in[1];
    float* out = (float*)d_out;

    // Param-space weights: duplicated lanes, zero-padded to 8-multiples.
    static BlurParams P = {};
    for (int ti = 0; ti < NT; ++ti)
        for (int j = 0; j < KW; ++j) {
            float w = (j < KT.nd[ti]) ? KT.w[ti][j] : 0.0f;
            P.K2[ti][j] = make_float2(w, w);
        }

    compute_perm<<<1, BATCH>>>(t);

    dim3 block(256);
    dim3 grid(IMG / 16, CHAN, BATCH);   // 16 x 3 x 64 = 3072 CTAs
    blur_fused<<<grid, block>>>(x, out, t, P);
}